// round 12
// baseline (speedup 1.0000x reference)
#include <cuda_runtime.h>
#include <math.h>

#define N_NODES 50000
#define N_EDGES 800000
#define NUM_RELS 16
#define H_DIM 128
#define LIN_DIM 512

#define CAP1 256
#define CAPE1 512
#define LOCE2 1024            // per-block local E2 staging (SMEM)

#define BM_WORDS ((N_NODES + 31) / 32)   // 1563

#define NB 148                 // 1 block/SM
#define NT 1024                // 32 warps/SM
#define NQ (N_EDGES / 4)       // 200000 int4 quads
#define QPB ((NQ + NB - 1) / NB)     // 1352 quads per block
#define GRP (NT / H_DIM)       // 8 k-groups for GEMV
#define KS  (H_DIM / GRP)      // 16 k's per group

#define NSALL  (N_NODES * NUM_RELS)      // 800000 floats
#define NSALL4 (NSALL / 4)               // 200000 float4
#define SCLR   128                       // blocks [SCLR..NB) clear S_all in P3
#define SCLRN  (NB - SCLR)               // 20 cleaner blocks
#define SCLRPB ((NSALL4 + SCLRN - 1) / SCLRN)

// -------- scratch (device globals; zero-init valid; self-cleaning per launch) --------
__device__ int          g_slot1[N_NODES];       // 0 = absent, slot+1
__device__ unsigned int g_bm1[BM_WORDS + 1];
__device__ int    g_n1, g_ne1;
__device__ int    g_s1_nodes[CAP1];
__device__ int    g_e1_src[CAPE1];
__device__ float2 g_cn[N_NODES];                // {norm, as_float(cls)} packed in P1
__device__ float  g_Sall[NSALL];                // cleared by idle blocks in P3
__device__ float  g_h2[CAP1 * H_DIM];           // cleared by block 3 in epilogue
__device__ float  g_root[H_DIM];                // cleared by block 0 in P1

// persistent-generation grid barrier
__device__ unsigned g_bar_cnt;
__device__ unsigned g_bar_gen;

__device__ __forceinline__ unsigned atom_add_release_gpu(unsigned* p, unsigned v) {
    unsigned old;
    asm volatile("atom.add.release.gpu.u32 %0, [%1], %2;"
                 : "=r"(old) : "l"(p), "r"(v) : "memory");
    return old;
}
__device__ __forceinline__ unsigned ld_acquire_gpu(unsigned* p) {
    unsigned v;
    asm volatile("ld.acquire.gpu.u32 %0, [%1];" : "=r"(v) : "l"(p) : "memory");
    return v;
}
__device__ __forceinline__ void st_release_gpu(unsigned* p, unsigned v) {
    asm volatile("st.release.gpu.u32 [%0], %1;" :: "l"(p), "r"(v) : "memory");
}

#define GRID_SYNC()                                                          \
    do {                                                                     \
        __syncthreads();                                                     \
        if (threadIdx.x == 0) {                                              \
            if (atom_add_release_gpu(&g_bar_cnt, 1u) == (unsigned)(NB - 1)) {\
                *(volatile unsigned*)&g_bar_cnt = 0u;                        \
                st_release_gpu(&g_bar_gen, my_gen + 1u);                     \
            } else {                                                         \
                int spin = 0;                                                \
                while (ld_acquire_gpu(&g_bar_gen) == my_gen)                 \
                    if (++spin > 64) __nanosleep(32);                        \
            }                                                                \
            my_gen++;                                                        \
        }                                                                    \
        __syncthreads();                                                     \
    } while (0)

__device__ __forceinline__ float warp_max_f(float v) {
#pragma unroll
    for (int o = 16; o > 0; o >>= 1) v = fmaxf(v, __shfl_down_sync(0xffffffffu, v, o));
    return v;
}
__device__ __forceinline__ float warp_sum_f(float v) {
#pragma unroll
    for (int o = 16; o > 0; o >>= 1) v += __shfl_down_sync(0xffffffffu, v, o);
    return v;
}

__global__ void __launch_bounds__(NT, 1) k_fused(
    const int* __restrict__ cls, const float* __restrict__ norm,
    const int* __restrict__ src, const int* __restrict__ dst,
    const float* __restrict__ W0, const float* __restrict__ W1,
    const float* __restrict__ W2,
    const float* __restrict__ a1_w, const float* __restrict__ a1_b,
    const float* __restrict__ a2_w, const float* __restrict__ a2_b,
    const float* __restrict__ c1_w, const float* __restrict__ c1_b,
    const float* __restrict__ c2_w, const float* __restrict__ c2_b,
    float* __restrict__ out, int out_size)
{
    const int tx  = threadIdx.x;
    const int bid = blockIdx.x;
    const int gt  = bid * NT + tx;

    const int q0     = bid * QPB;
    const int nq_blk = (NQ - q0 < QPB) ? (NQ - q0) : QPB;

    unsigned my_gen = 0;
    if (tx == 0) my_gen = ld_acquire_gpu(&g_bar_gen);

    __shared__ int4     sh_dst4[QPB + 1];          // 21.6 KB
    __shared__ unsigned sh_bm[BM_WORDS + 1];       // 6.3 KB
    __shared__ int      loc_src[LOCE2];            // 4 KB
    __shared__ int      loc_dsl[LOCE2];            // 4 KB
    __shared__ int      sh_e1[CAPE1];              // 2 KB
    __shared__ float    sh_h[H_DIM];
    __shared__ float    sh_p[NT];                  // 4 KB
    __shared__ float    s_hid[LIN_DIM];            // 2 KB
    __shared__ int      s_loc;
    __shared__ float    s_mx, s_sum;

    // ===== P1: pack cn; clear root; scan edges: S_all RED + (dst==0 -> S1/E1) =====
    {
        if (gt < N_NODES)
            g_cn[gt] = make_float2(norm[gt], __int_as_float(cls[gt]));
        if (bid == 0 && tx < H_DIM) g_root[tx] = 0.f;

#pragma unroll
        for (int half = 0; half < 2; half++) {
            int li = tx + half * NT;
            if (li < nq_blk) {
                int qi = q0 + li;
                const int4 d4 = reinterpret_cast<const int4*>(dst)[qi];
                sh_dst4[li] = d4;
                const int4 s4 = reinterpret_cast<const int4*>(src)[qi];
                int dv[4] = {d4.x, d4.y, d4.z, d4.w};
                int sv[4] = {s4.x, s4.y, s4.z, s4.w};
#pragma unroll
                for (int k = 0; k < 4; k++) {
                    int d = dv[k], s = sv[k];
                    float nm = norm[s];
                    int   c  = cls[s];
                    atomicAdd(&g_Sall[d * NUM_RELS + c], nm);   // RED, no return
                    if (d == 0) {
                        int p = atomicAdd(&g_ne1, 1);
                        if (p < CAPE1) g_e1_src[p] = s;
                        if (atomicCAS(&g_slot1[s], 0, -1) == 0) {
                            int sl = atomicAdd(&g_n1, 1);
                            if (sl < CAP1) g_s1_nodes[sl] = s;
                            g_slot1[s] = sl + 1;
                            atomicOr(&g_bm1[s >> 5], 1u << (s & 31));
                        }
                    }
                }
            }
        }
    }
    GRID_SYNC();   // barrier 1

    // ===== P2: SMEM re-scan -> local E2 hits -> per-hit msg1 GEMV -> h2 atomics =====
    {
        for (int i = tx; i <= BM_WORDS; i += NT) sh_bm[i] = g_bm1[i];
        if (tx == 0) s_loc = 0;
        __syncthreads();
#pragma unroll
        for (int half = 0; half < 2; half++) {
            int li = tx + half * NT;
            if (li < nq_blk) {
                int qi = q0 + li;
                const int4 d4 = sh_dst4[li];
                int dv[4] = {d4.x, d4.y, d4.z, d4.w};
#pragma unroll
                for (int k = 0; k < 4; k++) {
                    int d = dv[k];
                    if (sh_bm[d >> 5] & (1u << (d & 31))) {
                        int sl = g_slot1[d] - 1;
                        if (sl >= 0 && sl < CAP1) {
                            int p = atomicAdd(&s_loc, 1);
                            if (p < LOCE2) {
                                loc_src[p] = src[4 * qi + k];
                                loc_dsl[p] = sl;
                            }
                        }
                    }
                }
            }
        }
        __syncthreads();
        int nh = s_loc; if (nh > LOCE2) nh = LOCE2;
        const int j = tx & (H_DIM - 1), q = tx >> 7;
        for (int e = 0; e < nh; e++) {
            int s   = loc_src[e];
            int dsl = loc_dsl[e];
            if (tx < H_DIM) {
                const float* Sv = &g_Sall[s * NUM_RELS];
                float h = 0.f;
#pragma unroll
                for (int r = 0; r < NUM_RELS; r++)
                    h = fmaf(Sv[r], W0[(r * NUM_RELS + r) * H_DIM + tx], h);
                sh_h[tx] = fmaxf(h, 0.f);
            }
            __syncthreads();
            float2 cn = g_cn[s];
            int c = __float_as_int(cn.y);
            const float* Wc = W1 + c * H_DIM * H_DIM;
            float p = 0.f;
#pragma unroll
            for (int kk = 0; kk < KS; kk++) {
                int k = q * KS + kk;
                p = fmaf(sh_h[k], Wc[k * H_DIM + j], p);
            }
            sh_p[tx] = p;
            __syncthreads();
            if (tx < H_DIM) {
                float a = 0.f;
#pragma unroll
                for (int g = 0; g < GRP; g++) a += sh_p[tx + g * H_DIM];
                atomicAdd(&g_h2[dsl * H_DIM + tx], a * cn.x);
            }
            __syncthreads();
        }
    }
    GRID_SYNC();   // barrier 2

    // ===== P3: msg2 for S1 + root (blocks < n1); idle blocks clear S_all =====
    {
        int n1v = *(volatile int*)&g_n1; if (n1v > CAP1)  n1v = CAP1;
        int ne1 = *(volatile int*)&g_ne1; if (ne1 > CAPE1) ne1 = CAPE1;
        if (bid >= SCLR) {
            // clear S_all (dead after P2) — hidden behind msg2 work
            const float4 z4 = make_float4(0.f, 0.f, 0.f, 0.f);
            int s0 = (bid - SCLR) * SCLRPB;
            int sn = NSALL4 - s0; if (sn > SCLRPB) sn = SCLRPB;
            for (int i = tx; i < sn; i += NT)
                reinterpret_cast<float4*>(g_Sall)[s0 + i] = z4;
        } else if (bid < n1v) {
            for (int i = tx; i < ne1; i += NT) sh_e1[i] = g_e1_src[i];
            __syncthreads();
            const int j = tx & (H_DIM - 1), q = tx >> 7;
            for (int sl = bid; sl < n1v; sl += NB) {
                if (tx < H_DIM) sh_h[tx] = fmaxf(g_h2[sl * H_DIM + tx], 0.f);
                __syncthreads();
                int node = g_s1_nodes[sl];
                float2 cn = g_cn[node];
                int c = __float_as_int(cn.y);
                const float* Wc = W2 + c * H_DIM * H_DIM;
                float p = 0.f;
#pragma unroll
                for (int kk = 0; kk < KS; kk++) {
                    int k = q * KS + kk;
                    p = fmaf(sh_h[k], Wc[k * H_DIM + j], p);
                }
                sh_p[tx] = p;
                __syncthreads();
                if (tx < H_DIM) {
                    float a = 0.f;
#pragma unroll
                    for (int g = 0; g < GRP; g++) a += sh_p[tx + g * H_DIM];
                    a *= cn.x;
                    int mult = 0;
                    for (int i = 0; i < ne1; i++) mult += (sh_e1[i] == node);
                    if (mult > 0) atomicAdd(&g_root[tx], a * (float)mult);
                }
                __syncthreads();
            }
        }
    }

    // ===== last barrier: arrive (release); only blocks 0..3 wait =====
    __syncthreads();
    if (tx == 0) {
        if (atom_add_release_gpu(&g_bar_cnt, 1u) == (unsigned)(NB - 1)) {
            *(volatile unsigned*)&g_bar_cnt = 0u;
            st_release_gpu(&g_bar_gen, my_gen + 1u);
        } else if (bid < 4) {
            int spin = 0;
            while (ld_acquire_gpu(&g_bar_gen) == my_gen)
                if (++spin > 64) __nanosleep(32);
        }
        my_gen++;
    }
    __syncthreads();
    if (bid >= 4) return;

    // ===== epilogue: 2 cleans S1 state; 3 clears h2; 0/1 heads =====
    if (bid == 2) {
        int n1v = g_n1; if (n1v > CAP1) n1v = CAP1;
        for (int i = tx; i < n1v; i += NT) {
            int s = g_s1_nodes[i];
            g_slot1[s] = 0;
            g_bm1[s >> 5] = 0u;
        }
        __syncthreads();
        if (tx == 0) { g_n1 = 0; g_ne1 = 0; }
        return;
    }
    if (bid == 3) {
        const float4 z4 = make_float4(0.f, 0.f, 0.f, 0.f);
        for (int i = tx; i < (CAP1 * H_DIM) / 4; i += NT)
            reinterpret_cast<float4*>(g_h2)[i] = z4;
        return;
    }

    // blocks 0 (actor) and 1 (critic): softmax(root) locally, then head
    {
        const int t = tx;
        const int lane = t & 31;
        const int wid  = t >> 5;
        if (t < H_DIM) sh_h[t] = g_root[t];
        __syncthreads();
        if (wid == 0) {
            float m = fmaxf(fmaxf(sh_h[lane], sh_h[lane + 32]),
                            fmaxf(sh_h[lane + 64], sh_h[lane + 96]));
            m = warp_max_f(m);
            if (lane == 0) s_mx = m;
        }
        __syncthreads();
        if (t < H_DIM) sh_h[t] = expf(sh_h[t] - s_mx);
        __syncthreads();
        if (wid == 0) {
            float sm = sh_h[lane] + sh_h[lane + 32] + sh_h[lane + 64] + sh_h[lane + 96];
            sm = warp_sum_f(sm);
            if (lane == 0) s_sum = sm;
        }
        __syncthreads();
        if (t < H_DIM) sh_h[t] *= (1.f / s_sum);
        __syncthreads();

        if (bid == 0) {
            if (t < LIN_DIM) {
                float a = a1_b[t];
#pragma unroll 8
                for (int k = 0; k < H_DIM; k++) a = fmaf(sh_h[k], a1_w[k * LIN_DIM + t], a);
                s_hid[t] = fmaxf(a, 0.f);
            }
            __syncthreads();
            if (t < LIN_DIM) {
                int q = t >> 7, j = t & 127;
                const int k0 = q * 128;
                float p = 0.f;
#pragma unroll 8
                for (int k = 0; k < 128; k++)
                    p = fmaf(s_hid[k0 + k], a2_w[(k0 + k) * H_DIM + j], p);
                sh_p[t] = p;
            }
            __syncthreads();
            if (t < H_DIM)
                out[t] = a2_b[t] + sh_p[t] + sh_p[t + 128] + sh_p[t + 256] + sh_p[t + 384];
        } else {
            if (t < LIN_DIM) {
                float a = c1_b[t];
#pragma unroll 8
                for (int k = 0; k < H_DIM; k++) a = fmaf(sh_h[k], c1_w[k * LIN_DIM + t], a);
                s_hid[t] = fmaxf(a, 0.f);
            }
            __syncthreads();
            if (t < LIN_DIM) {
                float p = warp_sum_f(s_hid[t] * c2_w[t]);
                if (lane == 0) sh_p[wid] = p;
            }
            __syncthreads();
            if (t == 0) {
                float a = c2_b[0];
#pragma unroll
                for (int i = 0; i < 16; i++) a += sh_p[i];
                if (out_size > H_DIM) out[H_DIM] = a;
            }
        }
    }
}

// ---------------- launch ----------------
extern "C" void kernel_launch(void* const* d_in, const int* in_sizes, int n_in,
                              void* d_out, int out_size) {
    const int*   cls  = (const int*)  d_in[0];
    const float* norm = (const float*)d_in[1];
    const int*   src  = (const int*)  d_in[2];
    const int*   dst  = (const int*)  d_in[3];
    const float* W0   = (const float*)d_in[4];
    const float* W1   = (const float*)d_in[5];
    const float* W2   = (const float*)d_in[6];
    const float* a1_w = (const float*)d_in[7];
    const float* a1_b = (const float*)d_in[8];
    const float* a2_w = (const float*)d_in[9];
    const float* a2_b = (const float*)d_in[10];
    const float* c1_w = (const float*)d_in[11];
    const float* c1_b = (const float*)d_in[12];
    const float* c2_w = (const float*)d_in[13];
    const float* c2_b = (const float*)d_in[14];
    float* out = (float*)d_out;

    k_fused<<<NB, NT>>>(cls, norm, src, dst, W0, W1, W2,
                        a1_w, a1_b, a2_w, a2_b, c1_w, c1_b, c2_w, c2_b,
                        out, out_size);
}